// round 1
// baseline (speedup 1.0000x reference)
#include <cuda_runtime.h>
#include <math.h>

#define NB 32
#define NC 64
#define NH 128
#define NW 128
#define QD 8
#define HWSZ (NH*NW)
#define NEGV (-1e4f)

// ---- device scratch (static globals: allocation-free rule) ----
__device__ float g_Q[(size_t)NB*QD*HWSZ];     // [b][q][h][w]   16 MB
__device__ float g_K[(size_t)NB*QD*HWSZ];     // [b][q][h][w]   16 MB
__device__ float g_V[(size_t)NB*NC*HWSZ];     // [b][c][h][w]  128 MB
__device__ float g_MH[(size_t)NB*NC*QD*NW];   // [b][c*8+q][w]   8 MB
__device__ float g_MW[(size_t)NB*NH*NC*QD];   // [b][h][c*8+q]   8 MB

// ---------------------------------------------------------------
// Kernel A: fused 1x1 projections.  Q=softplus(wq@x+bq), K likewise, V=wv@x+bv
// one thread = one pixel, 80 fp32 accumulators, weights (transposed) in smem.
// ---------------------------------------------------------------
__global__ void __launch_bounds__(256) kproj(
    const float* __restrict__ x,
    const float* __restrict__ wq, const float* __restrict__ bq,
    const float* __restrict__ wk, const float* __restrict__ bk,
    const float* __restrict__ wv, const float* __restrict__ bv)
{
    __shared__ float swq[NC*QD];   // [c][o]
    __shared__ float swk[NC*QD];   // [c][o]
    __shared__ float swv[NC*NC];   // [c][o]
    int tid = threadIdx.x;
    for (int i = tid; i < NC*QD; i += 256) {
        int o = i / NC, c = i % NC;
        swq[c*QD + o] = wq[i];
        swk[c*QD + o] = wk[i];
    }
    for (int i = tid; i < NC*NC; i += 256) {
        int o = i / NC, c = i % NC;
        swv[c*NC + o] = wv[i];
    }
    __syncthreads();

    int gid = blockIdx.x * 256 + tid;
    int b = gid / HWSZ, p = gid % HWSZ;
    const float* xb = x + (size_t)b*NC*HWSZ + p;

    float aq[QD], ak[QD], av[NC];
#pragma unroll
    for (int o = 0; o < QD; o++) { aq[o] = bq[o]; ak[o] = bk[o]; }
#pragma unroll
    for (int o = 0; o < NC; o++) av[o] = bv[o];

#pragma unroll 2
    for (int c = 0; c < NC; c++) {
        float xv = xb[(size_t)c*HWSZ];
        const float4* wv4 = reinterpret_cast<const float4*>(&swv[c*NC]);
#pragma unroll
        for (int j = 0; j < NC/4; j++) {
            float4 wr = wv4[j];
            av[4*j+0] = fmaf(xv, wr.x, av[4*j+0]);
            av[4*j+1] = fmaf(xv, wr.y, av[4*j+1]);
            av[4*j+2] = fmaf(xv, wr.z, av[4*j+2]);
            av[4*j+3] = fmaf(xv, wr.w, av[4*j+3]);
        }
        const float4* wq4 = reinterpret_cast<const float4*>(&swq[c*QD]);
        const float4* wk4 = reinterpret_cast<const float4*>(&swk[c*QD]);
#pragma unroll
        for (int j = 0; j < QD/4; j++) {
            float4 a = wq4[j], kk = wk4[j];
            aq[4*j+0] = fmaf(xv, a.x,  aq[4*j+0]);
            aq[4*j+1] = fmaf(xv, a.y,  aq[4*j+1]);
            aq[4*j+2] = fmaf(xv, a.z,  aq[4*j+2]);
            aq[4*j+3] = fmaf(xv, a.w,  aq[4*j+3]);
            ak[4*j+0] = fmaf(xv, kk.x, ak[4*j+0]);
            ak[4*j+1] = fmaf(xv, kk.y, ak[4*j+1]);
            ak[4*j+2] = fmaf(xv, kk.z, ak[4*j+2]);
            ak[4*j+3] = fmaf(xv, kk.w, ak[4*j+3]);
        }
    }

    float* Qb = g_Q + (size_t)b*QD*HWSZ + p;
    float* Kb = g_K + (size_t)b*QD*HWSZ + p;
    float* Vb = g_V + (size_t)b*NC*HWSZ + p;
#pragma unroll
    for (int o = 0; o < QD; o++) {
        float vq = aq[o];
        Qb[(size_t)o*HWSZ] = fmaxf(vq, 0.f) + log1pf(expf(-fabsf(vq)));
        float vk = ak[o];
        Kb[(size_t)o*HWSZ] = fmaxf(vk, 0.f) + log1pf(expf(-fabsf(vk)));
    }
#pragma unroll
    for (int o = 0; o < NC; o++) Vb[(size_t)o*HWSZ] = av[o];
}

// ---------------------------------------------------------------
// Kernel B: M_W[b,h,c,q] = sum_w V[b,c,h,w] * K[b,q,h,w]
// one block per (b,h); V/K rows in smem (stride 129 to avoid conflicts)
// thread owns (c, q-pair) -> writes 2 contiguous outputs.
// ---------------------------------------------------------------
__global__ void __launch_bounds__(256) kmw()
{
    __shared__ float sV[NC*129];
    __shared__ float sK[QD*129];
    int tid = threadIdx.x;
    int b = blockIdx.x / NH, h = blockIdx.x % NH;
    const float* Vrow = g_V + (size_t)b*NC*HWSZ + h*NW;
    const float* Krow = g_K + (size_t)b*QD*HWSZ + h*NW;

#pragma unroll
    for (int i = 0; i < 8; i++) {
        int idx4 = tid + i*256;              // 2048 float4 = 64 rows * 32
        int c = idx4 >> 5, r = idx4 & 31;
        float4 v = *reinterpret_cast<const float4*>(Vrow + (size_t)c*HWSZ + r*4);
        sV[c*129 + r*4 + 0] = v.x; sV[c*129 + r*4 + 1] = v.y;
        sV[c*129 + r*4 + 2] = v.z; sV[c*129 + r*4 + 3] = v.w;
    }
    {
        int q = tid >> 5, r = tid & 31;      // 256 float4 = 8 rows * 32
        float4 v = *reinterpret_cast<const float4*>(Krow + (size_t)q*HWSZ + r*4);
        sK[q*129 + r*4 + 0] = v.x; sK[q*129 + r*4 + 1] = v.y;
        sK[q*129 + r*4 + 2] = v.z; sK[q*129 + r*4 + 3] = v.w;
    }
    __syncthreads();

    int c = tid >> 2;
    int q0 = (tid & 3) * 2;
    float a0 = 0.f, a1 = 0.f;
#pragma unroll 4
    for (int w = 0; w < NW; w++) {
        float v = sV[c*129 + w];
        a0 = fmaf(v, sK[q0*129 + w],     a0);
        a1 = fmaf(v, sK[(q0+1)*129 + w], a1);
    }
    float2* out = reinterpret_cast<float2*>(g_MW + ((size_t)b*NH + h)*NC*QD);
    out[tid] = make_float2(a0, a1);
}

// ---------------------------------------------------------------
// Kernel C: M_H[b,(c*8+q),w] = sum_h V[b,c,h,w] * K[b,q,h,w]
// one block per (b, w-tile of 32); h processed in chunks of 4 via smem;
// thread = (w lane, c-half) accumulates 16 (c,q) partials in registers.
// ---------------------------------------------------------------
__global__ void __launch_bounds__(1024) kmh()
{
    __shared__ float sV[NC*4*32];   // [c][hh][w]  32 KB
    __shared__ float sK[QD*4*32];   // [q][hh][w]   4 KB
    int tid = threadIdx.x;
    int b = blockIdx.x >> 2;
    int w0 = (blockIdx.x & 3) * 32;
    int w = tid & 31, ch = tid >> 5;     // ch in 0..31

    float acc[16];
#pragma unroll
    for (int i = 0; i < 16; i++) acc[i] = 0.f;

    const float* Vb = g_V + (size_t)b*NC*HWSZ + w0;
    const float* Kb = g_K + (size_t)b*QD*HWSZ + w0;

    for (int h0 = 0; h0 < NH; h0 += 4) {
        __syncthreads();
#pragma unroll
        for (int i = 0; i < 2; i++) {
            int idx4 = tid + i*1024;         // 2048 float4: 64c * 4hh * 8j
            int c = idx4 >> 5, rem = idx4 & 31;
            int hh = rem >> 3, j = rem & 7;
            float4 v = *reinterpret_cast<const float4*>(
                Vb + (size_t)c*HWSZ + (h0 + hh)*NW + j*4);
            *reinterpret_cast<float4*>(&sV[(c*4 + hh)*32 + j*4]) = v;
        }
        if (tid < 256) {
            int q = tid >> 5, rem = tid & 31;  // 256 float4: 8q * 4hh * 8j
            int hh = rem >> 3, j = rem & 7;
            float4 v = *reinterpret_cast<const float4*>(
                Kb + (size_t)q*HWSZ + (h0 + hh)*NW + j*4);
            *reinterpret_cast<float4*>(&sK[(q*4 + hh)*32 + j*4]) = v;
        }
        __syncthreads();
#pragma unroll
        for (int hh = 0; hh < 4; hh++) {
            float v0 = sV[(ch*4 + hh)*32 + w];
            float v1 = sV[((ch + 32)*4 + hh)*32 + w];
#pragma unroll
            for (int q = 0; q < QD; q++) {
                float kk = sK[(q*4 + hh)*32 + w];
                acc[q]     = fmaf(v0, kk, acc[q]);
                acc[8 + q] = fmaf(v1, kk, acc[8 + q]);
            }
        }
    }
    float* out = g_MH + (size_t)b*NC*QD*NW + w0 + w;
#pragma unroll
    for (int q = 0; q < QD; q++) {
        out[(size_t)(ch*QD + q)*NW]        = acc[q];
        out[(size_t)((ch + 32)*QD + q)*NW] = acc[8 + q];
    }
}

// ---------------------------------------------------------------
// Kernel D: out = gamma*( sum_q Q[q,h,w]*(MH[w,c,q]+MW[h,c,q]) + NEG*V ) + x
// one block per (b, 8h x 32w tile); MH tile [cq][32] + MW tile [h][cq] in
// dynamic smem (80 KB); Q in registers per thread; all global IO coalesced.
// ---------------------------------------------------------------
__global__ void __launch_bounds__(256) kout(
    const float* __restrict__ x,
    const float* __restrict__ gamma,
    float* __restrict__ out)
{
    extern __shared__ float dsm[];
    float* sMH = dsm;                  // [cq][32]   512*32 = 16384 floats
    float* sMW = dsm + NC*QD*32;       // [hl][cq]   8*512  =  4096 floats
    int tid = threadIdx.x;
    int w0 = blockIdx.x * 32, h0 = blockIdx.y * 8, b = blockIdx.z;
    int lane = tid & 31, hl = tid >> 5;

#pragma unroll
    for (int i = 0; i < 16; i++) {
        int idx4 = tid + i*256;        // 4096 float4: 512cq * 8j
        int cq = idx4 >> 3, j = idx4 & 7;
        float4 v = *reinterpret_cast<const float4*>(
            g_MH + ((size_t)b*NC*QD + cq)*NW + w0 + j*4);
        *reinterpret_cast<float4*>(&sMH[cq*32 + j*4]) = v;
    }
#pragma unroll
    for (int i = 0; i < 4; i++) {
        int idx4 = tid + i*256;        // 1024 float4: 8hh * 128j
        int hh = idx4 >> 7, j = idx4 & 127;
        float4 v = *reinterpret_cast<const float4*>(
            g_MW + ((size_t)b*NH + h0 + hh)*NC*QD + j*4);
        *reinterpret_cast<float4*>(&sMW[hh*512 + j*4]) = v;
    }

    int h = h0 + hl, w = w0 + lane;
    float Qr[QD];
#pragma unroll
    for (int q = 0; q < QD; q++)
        Qr[q] = g_Q[((size_t)b*QD + q)*HWSZ + h*NW + w];
    float gm = gamma[0];
    __syncthreads();

    const float* Vp = g_V + (size_t)b*NC*HWSZ + h*NW + w;
    const float* Xp = x   + (size_t)b*NC*HWSZ + h*NW + w;
    float*       Op = out + (size_t)b*NC*HWSZ + h*NW + w;

#pragma unroll 2
    for (int c = 0; c < NC; c++) {
        const float* mh = &sMH[(c*QD)*32 + lane];
        const float* mw = &sMW[hl*512 + c*QD];
        float4 mwa = *reinterpret_cast<const float4*>(mw);
        float4 mwb = *reinterpret_cast<const float4*>(mw + 4);
        float acc;
        acc  = (mh[0]       + mwa.x) * Qr[0];
        acc += (mh[32]      + mwa.y) * Qr[1];
        acc += (mh[64]      + mwa.z) * Qr[2];
        acc += (mh[96]      + mwa.w) * Qr[3];
        acc += (mh[128]     + mwb.x) * Qr[4];
        acc += (mh[160]     + mwb.y) * Qr[5];
        acc += (mh[192]     + mwb.z) * Qr[6];
        acc += (mh[224]     + mwb.w) * Qr[7];
        float v  = Vp[(size_t)c*HWSZ];
        float xv = Xp[(size_t)c*HWSZ];
        Op[(size_t)c*HWSZ] = fmaf(gm, fmaf(NEGV, v, acc), xv);
    }
}

// ---------------------------------------------------------------
extern "C" void kernel_launch(void* const* d_in, const int* in_sizes, int n_in,
                              void* d_out, int out_size)
{
    const float* x     = (const float*)d_in[0];
    const float* wq    = (const float*)d_in[1];
    const float* bq    = (const float*)d_in[2];
    const float* wk    = (const float*)d_in[3];
    const float* bk    = (const float*)d_in[4];
    const float* wv    = (const float*)d_in[5];
    const float* bv    = (const float*)d_in[6];
    const float* gamma = (const float*)d_in[7];
    float* out = (float*)d_out;

    cudaFuncSetAttribute(kout, cudaFuncAttributeMaxDynamicSharedMemorySize, 81920);

    kproj<<<(NB*HWSZ)/256, 256>>>(x, wq, bq, wk, bk, wv, bv);
    kmw<<<NB*NH, 256>>>();
    kmh<<<NB*4, 1024>>>();
    kout<<<dim3(NW/32, NH/8, NB), 256, 81920>>>(x, gamma, out);
}

// round 2
// speedup vs baseline: 1.4235x; 1.4235x over previous
#include <cuda_runtime.h>
#include <math.h>

#define NB 32
#define NC 64
#define NH 128
#define NW 128
#define QD 8
#define HWSZ (NH*NW)
#define NEGV (-1e4f)

// ---- device scratch ----
__device__ float g_Q[(size_t)NB*QD*HWSZ];     // [b][q][h][w]
__device__ float g_K[(size_t)NB*QD*HWSZ];     // [b][q][h][w]
__device__ float g_V[(size_t)NB*NC*HWSZ];     // [b][c][h][w]
__device__ float g_MH[(size_t)NB*NC*QD*NW];   // [b][c*8+q][w]
__device__ float g_MW[(size_t)NB*NH*NC*QD];   // [b][h][c*8+q]

// ---- packed f32x2 helpers (FFMA2 path, sm_10x) ----
__device__ __forceinline__ unsigned long long pack2(float a, float b) {
    unsigned long long r;
    asm("mov.b64 %0, {%1, %2};" : "=l"(r) : "f"(a), "f"(b));
    return r;
}
__device__ __forceinline__ void unpack2(unsigned long long v, float& a, float& b) {
    asm("mov.b64 {%0, %1}, %2;" : "=f"(a), "=f"(b) : "l"(v));
}
__device__ __forceinline__ void ffma2(unsigned long long& d,
                                      unsigned long long a, unsigned long long b) {
    asm("fma.rn.f32x2 %0, %1, %2, %0;" : "+l"(d) : "l"(a), "l"(b));
}

// ---------------------------------------------------------------
// Kernel A: fused 1x1 projections with packed f32x2 accumulation.
// one thread = one pixel; accumulators hold OUTPUT PAIRS (o,o+1) packed,
// weights read from smem as 16B vectors (pairs are naturally adjacent in o).
// ---------------------------------------------------------------
__global__ void __launch_bounds__(256, 2) kproj(
    const float* __restrict__ x,
    const float* __restrict__ wq, const float* __restrict__ bq,
    const float* __restrict__ wk, const float* __restrict__ bk,
    const float* __restrict__ wv, const float* __restrict__ bv)
{
    __shared__ __align__(16) float swq[NC*QD];   // [c][o]
    __shared__ __align__(16) float swk[NC*QD];   // [c][o]
    __shared__ __align__(16) float swv[NC*NC];   // [c][o]
    int tid = threadIdx.x;
    for (int i = tid; i < NC*QD; i += 256) {
        int o = i / NC, c = i % NC;
        swq[c*QD + o] = wq[i];
        swk[c*QD + o] = wk[i];
    }
    for (int i = tid; i < NC*NC; i += 256) {
        int o = i / NC, c = i % NC;
        swv[c*NC + o] = wv[i];
    }
    __syncthreads();

    int gid = blockIdx.x * 256 + tid;
    int b = gid / HWSZ, p = gid % HWSZ;
    const float* xb = x + (size_t)b*NC*HWSZ + p;

    unsigned long long aq[QD/2], ak[QD/2], av[NC/2];
#pragma unroll
    for (int j = 0; j < QD/2; j++) {
        aq[j] = pack2(bq[2*j], bq[2*j+1]);
        ak[j] = pack2(bk[2*j], bk[2*j+1]);
    }
#pragma unroll
    for (int j = 0; j < NC/2; j++) av[j] = pack2(bv[2*j], bv[2*j+1]);

#pragma unroll 2
    for (int c = 0; c < NC; c++) {
        float xv = xb[(size_t)c*HWSZ];
        unsigned long long xv2 = pack2(xv, xv);
        const ulonglong2* wv2 = reinterpret_cast<const ulonglong2*>(&swv[c*NC]);
#pragma unroll
        for (int j = 0; j < NC/4; j++) {
            ulonglong2 wp = wv2[j];
            ffma2(av[2*j+0], xv2, wp.x);
            ffma2(av[2*j+1], xv2, wp.y);
        }
        const ulonglong2* wq2 = reinterpret_cast<const ulonglong2*>(&swq[c*QD]);
        const ulonglong2* wk2 = reinterpret_cast<const ulonglong2*>(&swk[c*QD]);
#pragma unroll
        for (int j = 0; j < QD/4; j++) {
            ulonglong2 a = wq2[j], kk = wk2[j];
            ffma2(aq[2*j+0], xv2, a.x);
            ffma2(aq[2*j+1], xv2, a.y);
            ffma2(ak[2*j+0], xv2, kk.x);
            ffma2(ak[2*j+1], xv2, kk.y);
        }
    }

    float* Qb = g_Q + (size_t)b*QD*HWSZ + p;
    float* Kb = g_K + (size_t)b*QD*HWSZ + p;
    float* Vb = g_V + (size_t)b*NC*HWSZ + p;
#pragma unroll
    for (int j = 0; j < QD/2; j++) {
        float v0, v1;
        unpack2(aq[j], v0, v1);
        Qb[(size_t)(2*j+0)*HWSZ] = fmaxf(v0, 0.f) + log1pf(expf(-fabsf(v0)));
        Qb[(size_t)(2*j+1)*HWSZ] = fmaxf(v1, 0.f) + log1pf(expf(-fabsf(v1)));
        unpack2(ak[j], v0, v1);
        Kb[(size_t)(2*j+0)*HWSZ] = fmaxf(v0, 0.f) + log1pf(expf(-fabsf(v0)));
        Kb[(size_t)(2*j+1)*HWSZ] = fmaxf(v1, 0.f) + log1pf(expf(-fabsf(v1)));
    }
#pragma unroll
    for (int j = 0; j < NC/2; j++) {
        float v0, v1;
        unpack2(av[j], v0, v1);
        Vb[(size_t)(2*j+0)*HWSZ] = v0;
        Vb[(size_t)(2*j+1)*HWSZ] = v1;
    }
}

// ---------------------------------------------------------------
// Kernel B: M_W[b,h,c,q] = sum_w V[b,c,h,w] * K[b,q,h,w]
// ---------------------------------------------------------------
__global__ void __launch_bounds__(256) kmw()
{
    __shared__ float sV[NC*129];
    __shared__ float sK[QD*129];
    int tid = threadIdx.x;
    int b = blockIdx.x / NH, h = blockIdx.x % NH;
    const float* Vrow = g_V + (size_t)b*NC*HWSZ + h*NW;
    const float* Krow = g_K + (size_t)b*QD*HWSZ + h*NW;

#pragma unroll
    for (int i = 0; i < 8; i++) {
        int idx4 = tid + i*256;
        int c = idx4 >> 5, r = idx4 & 31;
        float4 v = *reinterpret_cast<const float4*>(Vrow + (size_t)c*HWSZ + r*4);
        sV[c*129 + r*4 + 0] = v.x; sV[c*129 + r*4 + 1] = v.y;
        sV[c*129 + r*4 + 2] = v.z; sV[c*129 + r*4 + 3] = v.w;
    }
    {
        int q = tid >> 5, r = tid & 31;
        float4 v = *reinterpret_cast<const float4*>(Krow + (size_t)q*HWSZ + r*4);
        sK[q*129 + r*4 + 0] = v.x; sK[q*129 + r*4 + 1] = v.y;
        sK[q*129 + r*4 + 2] = v.z; sK[q*129 + r*4 + 3] = v.w;
    }
    __syncthreads();

    int c = tid >> 2;
    int q0 = (tid & 3) * 2;
    float a0 = 0.f, a1 = 0.f;
#pragma unroll 4
    for (int w = 0; w < NW; w++) {
        float v = sV[c*129 + w];
        a0 = fmaf(v, sK[q0*129 + w],     a0);
        a1 = fmaf(v, sK[(q0+1)*129 + w], a1);
    }
    float2* out = reinterpret_cast<float2*>(g_MW + ((size_t)b*NH + h)*NC*QD);
    out[tid] = make_float2(a0, a1);
}

// ---------------------------------------------------------------
// Kernel C: M_H[b,(c*8+q),w] = sum_h V[b,c,h,w] * K[b,q,h,w]
// ---------------------------------------------------------------
__global__ void __launch_bounds__(1024) kmh()
{
    __shared__ float sV[NC*4*32];
    __shared__ float sK[QD*4*32];
    int tid = threadIdx.x;
    int b = blockIdx.x >> 2;
    int w0 = (blockIdx.x & 3) * 32;
    int w = tid & 31, ch = tid >> 5;

    float acc[16];
#pragma unroll
    for (int i = 0; i < 16; i++) acc[i] = 0.f;

    const float* Vb = g_V + (size_t)b*NC*HWSZ + w0;
    const float* Kb = g_K + (size_t)b*QD*HWSZ + w0;

    for (int h0 = 0; h0 < NH; h0 += 4) {
        __syncthreads();
#pragma unroll
        for (int i = 0; i < 2; i++) {
            int idx4 = tid + i*1024;
            int c = idx4 >> 5, rem = idx4 & 31;
            int hh = rem >> 3, j = rem & 7;
            float4 v = *reinterpret_cast<const float4*>(
                Vb + (size_t)c*HWSZ + (h0 + hh)*NW + j*4);
            *reinterpret_cast<float4*>(&sV[(c*4 + hh)*32 + j*4]) = v;
        }
        if (tid < 256) {
            int q = tid >> 5, rem = tid & 31;
            int hh = rem >> 3, j = rem & 7;
            float4 v = *reinterpret_cast<const float4*>(
                Kb + (size_t)q*HWSZ + (h0 + hh)*NW + j*4);
            *reinterpret_cast<float4*>(&sK[(q*4 + hh)*32 + j*4]) = v;
        }
        __syncthreads();
#pragma unroll
        for (int hh = 0; hh < 4; hh++) {
            float v0 = sV[(ch*4 + hh)*32 + w];
            float v1 = sV[((ch + 32)*4 + hh)*32 + w];
#pragma unroll
            for (int q = 0; q < QD; q++) {
                float kk = sK[(q*4 + hh)*32 + w];
                acc[q]     = fmaf(v0, kk, acc[q]);
                acc[8 + q] = fmaf(v1, kk, acc[8 + q]);
            }
        }
    }
    float* out = g_MH + (size_t)b*NC*QD*NW + w0 + w;
#pragma unroll
    for (int q = 0; q < QD; q++) {
        out[(size_t)(ch*QD + q)*NW]        = acc[q];
        out[(size_t)((ch + 32)*QD + q)*NW] = acc[8 + q];
    }
}

// ---------------------------------------------------------------
// Kernel D: out = gamma*( sum_q Q*(MH+MW) + NEG*V ) + x
// Block = (b, c-half of 32, 8h x 32w). 40KB static smem -> 5 CTAs/SM.
// c-loop unrolled by 4 with batched V/x loads for MLP.
// ---------------------------------------------------------------
__global__ void __launch_bounds__(256, 5) kout(
    const float* __restrict__ x,
    const float* __restrict__ gamma,
    float* __restrict__ out)
{
    __shared__ __align__(16) float sMH[32*QD*32];   // [c_loc*8+q][w32]  32KB
    __shared__ __align__(16) float sMW[8*32*QD];    // [hl][c_loc*8+q]    8KB
    int tid = threadIdx.x;
    int w0 = blockIdx.x * 32, h0 = blockIdx.y * 8;
    int b  = blockIdx.z >> 1;
    int c0 = (blockIdx.z & 1) * 32;
    int lane = tid & 31, hl = tid >> 5;

    // MH half-tile: 256 cq_loc x 32 w = 8192 floats = 2048 float4
#pragma unroll
    for (int i = 0; i < 8; i++) {
        int idx4 = tid + i*256;
        int cql = idx4 >> 3, j = idx4 & 7;
        float4 v = *reinterpret_cast<const float4*>(
            g_MH + ((size_t)b*NC*QD + c0*QD + cql)*NW + w0 + j*4);
        *reinterpret_cast<float4*>(&sMH[cql*32 + j*4]) = v;
    }
    // MW half-tile: 8 h x 256 = 2048 floats = 512 float4
#pragma unroll
    for (int i = 0; i < 2; i++) {
        int idx4 = tid + i*256;
        int hh = idx4 >> 6, j = idx4 & 63;
        float4 v = *reinterpret_cast<const float4*>(
            g_MW + ((size_t)(b*NH + h0 + hh)*NC + c0)*QD + j*4);
        *reinterpret_cast<float4*>(&sMW[hh*(32*QD) + j*4]) = v;
    }

    int h = h0 + hl, w = w0 + lane;
    float Qr[QD];
#pragma unroll
    for (int q = 0; q < QD; q++)
        Qr[q] = g_Q[((size_t)b*QD + q)*HWSZ + h*NW + w];
    float gm = gamma[0];
    __syncthreads();

    const float* Vp = g_V + ((size_t)b*NC + c0)*HWSZ + h*NW + w;
    const float* Xp = x   + ((size_t)b*NC + c0)*HWSZ + h*NW + w;
    float*       Op = out + ((size_t)b*NC + c0)*HWSZ + h*NW + w;

#pragma unroll
    for (int cc = 0; cc < 32; cc += 4) {
        float v[4], xr[4];
#pragma unroll
        for (int u = 0; u < 4; u++) {
            v[u]  = Vp[(size_t)(cc+u)*HWSZ];
            xr[u] = Xp[(size_t)(cc+u)*HWSZ];
        }
#pragma unroll
        for (int u = 0; u < 4; u++) {
            int c = cc + u;
            const float* mh = &sMH[c*QD*32 + lane];
            const float4* mwp = reinterpret_cast<const float4*>(&sMW[hl*(32*QD) + c*QD]);
            float4 a = mwp[0], bb = mwp[1];
            float acc;
            acc  = (mh[0]   + a.x)  * Qr[0];
            acc += (mh[32]  + a.y)  * Qr[1];
            acc += (mh[64]  + a.z)  * Qr[2];
            acc += (mh[96]  + a.w)  * Qr[3];
            acc += (mh[128] + bb.x) * Qr[4];
            acc += (mh[160] + bb.y) * Qr[5];
            acc += (mh[192] + bb.z) * Qr[6];
            acc += (mh[224] + bb.w) * Qr[7];
            Op[(size_t)c*HWSZ] = fmaf(gm, fmaf(NEGV, v[u], acc), xr[u]);
        }
    }
}

// ---------------------------------------------------------------
extern "C" void kernel_launch(void* const* d_in, const int* in_sizes, int n_in,
                              void* d_out, int out_size)
{
    const float* x     = (const float*)d_in[0];
    const float* wq    = (const float*)d_in[1];
    const float* bq    = (const float*)d_in[2];
    const float* wk    = (const float*)d_in[3];
    const float* bk    = (const float*)d_in[4];
    const float* wv    = (const float*)d_in[5];
    const float* bv    = (const float*)d_in[6];
    const float* gamma = (const float*)d_in[7];
    float* out = (float*)d_out;

    kproj<<<(NB*HWSZ)/256, 256>>>(x, wq, bq, wk, bk, wv, bv);
    kmw<<<NB*NH, 256>>>();
    kmh<<<NB*4, 1024>>>();
    kout<<<dim3(NW/32, NH/8, NB*2), 256>>>(x, gamma, out);
}